// round 11
// baseline (speedup 1.0000x reference)
#include <cuda_runtime.h>
#include <cuda_bf16.h>

// Reference output is identically zero: with factor=2, the reference pads the
// SIZE-1 dim1 of y.reshape(-1,1,Hf,Wf) by (1,0) and the subsequent slice
// [:, 0:1] selects the zero-pad slice, discarding all data (symbolic proof R1;
// rel_err=0 in all passing rounds). Work = write 102,760,448 float zeros.
//
// Kernel time is pinned at the ~6.34 TB/s DRAM-write floor (55.3-55.5us across
// all variants). The only movement left is launch/dispatch overhead, which
// improved going 25K -> 12.5K blocks (R9 58.11 -> R10 57.82 total). This
// round takes the final step: 16 float4s/thread, 64KB tile, 6,272 blocks
// (still ~5 waves of fire-and-exit CTAs — far from R4's failed persistent form).

__global__ void __launch_bounds__(256) zero_fill_v4x16(float4* __restrict__ out,
                                                       long long n4) {
    const float4 z = make_float4(0.f, 0.f, 0.f, 0.f);
    // Block tile: 4096 float4s (64 KB); 16 coalesced 512B bursts per warp,
    // fully unrolled straight-line stores (no loop-carried branch).
    long long base = (long long)blockIdx.x * 4096 + threadIdx.x;
#pragma unroll
    for (int j = 0; j < 16; j++) {
        long long idx = base + (long long)j * 256;
        if (idx < n4) out[idx] = z;
    }
}

// Scalar tail for out_size % 4 != 0 (dead for this shape; kept for generality).
__global__ void zero_fill_tail(float* __restrict__ out,
                               long long start, long long n_total) {
    long long i = start + (long long)blockIdx.x * blockDim.x + threadIdx.x;
    if (i < n_total) out[i] = 0.f;
}

extern "C" void kernel_launch(void* const* d_in, const int* in_sizes, int n_in,
                              void* d_out, int out_size) {
    (void)d_in; (void)in_sizes; (void)n_in;

    long long n_total = (long long)out_size;   // 102,760,448 expected
    long long n4 = n_total / 4;                // 25,690,112 float4s

    const int threads = 256;
    long long blocks = (n4 + 4095) / 4096;     // 6,272 blocks expected

    if (blocks > 0) {
        zero_fill_v4x16<<<(unsigned)blocks, threads>>>((float4*)d_out, n4);
    }

    long long tail = n_total - n4 * 4;         // 0 for this shape
    if (tail > 0) {
        zero_fill_tail<<<1, 256>>>((float*)d_out, n4 * 4, n_total);
    }
}

// round 12
// speedup vs baseline: 1.0081x; 1.0081x over previous
#include <cuda_runtime.h>
#include <cuda_bf16.h>

// FINAL — frozen at the measured optimum (R10 configuration: 57.82us total,
// 55.46us kernel, DRAM=80.0%, 6.34 TB/s, occ=82.1%).
//
// Reference output is identically zero: with factor=2, the reference pads the
// SIZE-1 dim1 of y.reshape(-1,1,Hf,Wf) by (1,0) and the subsequent slice
// [:, 0:1] selects the zero-pad slice, discarding all data (symbolic proof R1;
// rel_err=0 in every passing round). Work = write 102,760,448 float zeros.
//
// Granularity curve (fully mapped, unimodal):
//   100,352 blocks x 1 f4 : 55.68us kernel / 58.11 total
//    25,088 blocks x 4 f4 : 55.30-55.49   / 58.08-58.11
//    12,544 blocks x 8 f4 : 55.46         / 57.82   <- optimum, this file
//     6,272 blocks x16 f4 : 56.74         / 59.65   (wave quantization)
//     1,184 persistent    : 66.82         / 67.68   (store-MLP starved)
// Kernel time is pinned at the ~6.34 TB/s DRAM-write hardware floor; memset
// and __stcs variants confirmed no faster path exists.

__global__ void __launch_bounds__(256) zero_fill_v4x8(float4* __restrict__ out,
                                                      long long n4) {
    const float4 z = make_float4(0.f, 0.f, 0.f, 0.f);
    // Block tile: 2048 float4s (32 KB); 8 coalesced 512B bursts per warp.
    long long base = (long long)blockIdx.x * 2048 + threadIdx.x;
#pragma unroll
    for (int j = 0; j < 8; j++) {
        long long idx = base + (long long)j * 256;
        if (idx < n4) out[idx] = z;
    }
}

// Scalar tail for out_size % 4 != 0 (dead for this shape; kept for generality).
__global__ void zero_fill_tail(float* __restrict__ out,
                               long long start, long long n_total) {
    long long i = start + (long long)blockIdx.x * blockDim.x + threadIdx.x;
    if (i < n_total) out[i] = 0.f;
}

extern "C" void kernel_launch(void* const* d_in, const int* in_sizes, int n_in,
                              void* d_out, int out_size) {
    (void)d_in; (void)in_sizes; (void)n_in;

    long long n_total = (long long)out_size;   // 102,760,448 expected
    long long n4 = n_total / 4;                // 25,690,112 float4s

    const int threads = 256;
    long long blocks = (n4 + 2047) / 2048;     // 12,544 blocks expected

    if (blocks > 0) {
        zero_fill_v4x8<<<(unsigned)blocks, threads>>>((float4*)d_out, n4);
    }

    long long tail = n_total - n4 * 4;         // 0 for this shape
    if (tail > 0) {
        zero_fill_tail<<<1, 256>>>((float*)d_out, n4 * 4, n_total);
    }
}

// round 14
// speedup vs baseline: 1.0315x; 1.0232x over previous
#include <cuda_runtime.h>
#include <cuda_bf16.h>

// FINAL (terminal freeze — session converged).
//
// Reference output is identically zero: with factor=2, the reference pads the
// SIZE-1 dim1 of y.reshape(-1,1,Hf,Wf) by (1,0) and the subsequent slice
// [:, 0:1] selects the zero-pad slice, discarding all data (symbolic proof R1;
// rel_err=0 in every passing round). Work = write 102,760,448 float zeros.
//
// Twelve-round conclusion: every fire-and-exit store kernel sits at the
// ~6.3 TB/s DRAM-write hardware floor (kernel 55.3-56.0us, DRAM 78-80%).
// Identical-source runs (R10 vs R12) differ by 1.35us total -> noise band
// +/-0.7us; no variant differences within it are real. Only measurable
// effects were regressions: persistent CTAs (+11us), 16xf4 tiles (+1.3us).
// memset, __stcs, predication, vector width, 12.5K-100K block counts: noise.
//
// Config: 12,544 CTAs x 256 threads, 8 coalesced float4 (STG.E.128) stores
// per thread (32KB tile), ~10.6 waves of fire-and-exit CTAs.

__global__ void __launch_bounds__(256) zero_fill_v4x8(float4* __restrict__ out,
                                                      long long n4) {
    const float4 z = make_float4(0.f, 0.f, 0.f, 0.f);
    long long base = (long long)blockIdx.x * 2048 + threadIdx.x;
#pragma unroll
    for (int j = 0; j < 8; j++) {
        long long idx = base + (long long)j * 256;
        if (idx < n4) out[idx] = z;
    }
}

// Scalar tail for out_size % 4 != 0 (dead for this shape; kept for generality).
__global__ void zero_fill_tail(float* __restrict__ out,
                               long long start, long long n_total) {
    long long i = start + (long long)blockIdx.x * blockDim.x + threadIdx.x;
    if (i < n_total) out[i] = 0.f;
}

extern "C" void kernel_launch(void* const* d_in, const int* in_sizes, int n_in,
                              void* d_out, int out_size) {
    (void)d_in; (void)in_sizes; (void)n_in;

    long long n_total = (long long)out_size;   // 102,760,448 expected
    long long n4 = n_total / 4;                // 25,690,112 float4s

    const int threads = 256;
    long long blocks = (n4 + 2047) / 2048;     // 12,544 blocks expected

    if (blocks > 0) {
        zero_fill_v4x8<<<(unsigned)blocks, threads>>>((float4*)d_out, n4);
    }

    long long tail = n_total - n4 * 4;         // 0 for this shape
    if (tail > 0) {
        zero_fill_tail<<<1, 256>>>((float*)d_out, n4 * 4, n_total);
    }
}